// round 1
// baseline (speedup 1.0000x reference)
#include <cuda_runtime.h>
#include <cstdint>

#define BATCH 64
#define KPTS  2048
#define TJ    512
#define RI    4
#define NTHR  128
#define TI    (NTHR * RI)        // 512
#define NI    (KPTS / TI)        // 4
#define NJ    (KPTS / TJ)        // 4
#define DUP   64                 // duplicated wrap region for lane-staggered j
#define INF_BITS 0x7f800000

typedef unsigned long long ull;

// scratch (device globals: allocation-free per harness rules)
__device__ int   g_row[BATCH * KPTS];
__device__ int   g_col[BATCH * KPTS];
__device__ float g_part[256];

// ---------- f32x2 packed helpers ----------
__device__ __forceinline__ ull pk(float a, float b) {
    ull r; asm("mov.b64 %0, {%1,%2};" : "=l"(r) : "f"(a), "f"(b)); return r;
}
__device__ __forceinline__ void upk(ull v, float& a, float& b) {
    asm("mov.b64 {%0,%1}, %2;" : "=f"(a), "=f"(b) : "l"(v));
}
__device__ __forceinline__ ull fma2(ull a, ull b, ull c) {
    ull d; asm("fma.rn.f32x2 %0, %1, %2, %3;" : "=l"(d) : "l"(a), "l"(b), "l"(c)); return d;
}
__device__ __forceinline__ ull add2(ull a, ull b) {
    ull d; asm("add.rn.f32x2 %0, %1, %2;" : "=l"(d) : "l"(a), "l"(b)); return d;
}

// ---------- kernel 0: init minima to +inf bits ----------
__global__ void init_kernel() {
    int idx = blockIdx.x * blockDim.x + threadIdx.x;
    if (idx < BATCH * KPTS) {
        g_row[idx] = INF_BITS;
        g_col[idx] = INF_BITS;
    }
}

// ---------- kernel 1: main pairwise min ----------
// v_ij = t2_j - 2 px_i tx_j - 2 py_i ty_j   (squared dist = p2_i + v_ij)
// rowmin_i = p2_i + min_j v_ij  (fold p2 at end — no add in loop)
// colmin_j = min_i (p2_i + v_ij) (one packed add per 2 pairs)
// All cross-thread mins done as s32 on float bits; clamp to 0 at sqrt time.
__global__ void __launch_bounds__(NTHR)
chamfer_main(const float* __restrict__ P, const float* __restrict__ T) {
    __shared__ ulonglong2 sA[TJ + DUP];   // {(-2tx,-2tx), (-2ty,-2ty)}
    __shared__ ull        sB[TJ + DUP];   // {t2, t2}
    __shared__ int        sCol[TJ + DUP]; // partial colmin (float bits, s32 min)

    const int b  = blockIdx.z;
    const int ic = blockIdx.y;
    const int jc = blockIdx.x;
    const int tid = threadIdx.x;

    const float* Pb = P + b * (2 * KPTS);
    const float* Tb = T + b * (2 * KPTS);
    const int jbase = jc * TJ;

    // stage target tile (with DUP-entry wrap duplication)
    for (int t = tid; t < TJ + DUP; t += NTHR) {
        int j = jbase + (t & (TJ - 1));
        float tx = Tb[j];
        float ty = Tb[KPTS + j];
        float m2x = -2.0f * tx, m2y = -2.0f * ty;
        sA[t] = make_ulonglong2(pk(m2x, m2x), pk(m2y, m2y));
        float t2 = tx * tx + ty * ty;
        sB[t] = pk(t2, t2);
        sCol[t] = INF_BITS;
    }

    // per-thread predicted points (4 consecutive i, vectorized load)
    const int i0 = ic * TI + tid * RI;
    float4 x4 = *reinterpret_cast<const float4*>(Pb + i0);
    float4 y4 = *reinterpret_cast<const float4*>(Pb + KPTS + i0);
    ull px01 = pk(x4.x, x4.y), px23 = pk(x4.z, x4.w);
    ull py01 = pk(y4.x, y4.y), py23 = pk(y4.z, y4.w);
    float p2a = x4.x * x4.x + y4.x * y4.x;
    float p2b = x4.y * x4.y + y4.y * y4.y;
    float p2c = x4.z * x4.z + y4.z * y4.z;
    float p2d = x4.w * x4.w + y4.w * y4.w;
    ull pp01 = pk(p2a, p2b), pp23 = pk(p2c, p2d);

    const float FINF = __int_as_float(INF_BITS);
    float r0 = FINF, r1 = FINF, r2 = FINF, r3 = FINF;

    // lane-staggered start: intra-warp distinct j (conflict-free LDS + spread ATOMS),
    // warps offset by 8 to decorrelate cross-warp atomics.
    const int off = (tid & 31) + ((tid >> 5) << 3);   // 0..55  (< DUP)

    __syncthreads();

#pragma unroll 8
    for (int jt = 0; jt < TJ; ++jt) {
        const int idx = off + jt;
        ulonglong2 A = sA[idx];      // LDS.128
        ull c2       = sB[idx];      // LDS.64

        ull v0 = fma2(py01, A.y, fma2(px01, A.x, c2));
        ull v1 = fma2(py23, A.y, fma2(px23, A.x, c2));

        float a, bb, c, d;
        upk(v0, a, bb); upk(v1, c, d);
        r0 = fminf(r0, a); r1 = fminf(r1, bb);
        r2 = fminf(r2, c); r3 = fminf(r3, d);

        ull w0 = add2(v0, pp01);
        ull w1 = add2(v1, pp23);
        float e, f, g, h;
        upk(w0, e, f); upk(w1, g, h);
        float m = fminf(fminf(e, f), fminf(g, h));

        atomicMin(&sCol[idx], __float_as_int(m));   // spread-address ATOMS
    }

    __syncthreads();

    // fold wrap duplicates back
    if (tid < DUP) {
        int v = sCol[TJ + tid];
        if (v < sCol[tid]) sCol[tid] = v;   // exclusive after barrier
    }
    __syncthreads();

    // publish block partials
    for (int t = tid; t < TJ; t += NTHR)
        atomicMin(&g_col[b * KPTS + jbase + t], sCol[t]);

    atomicMin(&g_row[b * KPTS + i0 + 0], __float_as_int(p2a + r0));
    atomicMin(&g_row[b * KPTS + i0 + 1], __float_as_int(p2b + r1));
    atomicMin(&g_row[b * KPTS + i0 + 2], __float_as_int(p2c + r2));
    atomicMin(&g_row[b * KPTS + i0 + 3], __float_as_int(p2d + r3));
}

// ---------- kernel 2: deterministic partial sums of sqrt(max(d2,0)) ----------
__global__ void reduce1() {
    __shared__ float ss[256];
    const int total = BATCH * KPTS;           // per array
    int base = blockIdx.x * 1024;
    float s = 0.0f;
    for (int t = threadIdx.x; t < 1024; t += 256) {
        int e = base + t;
        int bits = (e < total) ? g_row[e] : g_col[e - total];
        float f = fmaxf(__int_as_float(bits), 0.0f);
        s += sqrtf(f);
    }
    ss[threadIdx.x] = s;
    __syncthreads();
    for (int st = 128; st > 0; st >>= 1) {
        if (threadIdx.x < st) ss[threadIdx.x] += ss[threadIdx.x + st];
        __syncthreads();
    }
    if (threadIdx.x == 0) g_part[blockIdx.x] = ss[0];
}

// ---------- kernel 3: final deterministic sum ----------
__global__ void reduce2(float* out) {
    __shared__ float ss[256];
    ss[threadIdx.x] = g_part[threadIdx.x];
    __syncthreads();
    for (int st = 128; st > 0; st >>= 1) {
        if (threadIdx.x < st) ss[threadIdx.x] += ss[threadIdx.x + st];
        __syncthreads();
    }
    if (threadIdx.x == 0)
        out[0] = ss[0] * (1.0f / (float)(BATCH * KPTS));
}

extern "C" void kernel_launch(void* const* d_in, const int* in_sizes, int n_in,
                              void* d_out, int out_size) {
    const float* P = (const float*)d_in[0];   // predicted (64, 4096)
    const float* T = (const float*)d_in[1];   // target    (64, 4096)
    (void)in_sizes; (void)n_in; (void)out_size;

    init_kernel<<<(BATCH * KPTS + 255) / 256, 256>>>();
    dim3 grid(NJ, NI, BATCH);                 // 4 x 4 x 64 = 1024 blocks
    chamfer_main<<<grid, NTHR>>>(P, T);
    reduce1<<<(2 * BATCH * KPTS) / 1024, 256>>>();
    reduce2<<<1, 256>>>((float*)d_out);
}